// round 14
// baseline (speedup 1.0000x reference)
#include <cuda_runtime.h>
#include <cuda_bf16.h>

// ---------------- problem constants ----------------
#define S_LEN    661500
#define HOP      512
#define NFFT     2048
#define T_FRAMES 1292
#define N_BINS   1025
#define N_MELS   128
#define BW       96                // mel band window cap
#define BW2      (BW / 2)          // float2 chunks
#define PWS      1088              // power row stride (34*32)
#define PWBASE   32                // pw starts 32 floats in (neg-align guard)

// smem skews (index units: float2)
#define SKD(i) ((i) + ((i) >> 4))  // data arrays
#define SKT(i) ((i) + ((i) >> 3))  // twiddle table

#define A2   (SKD(2047) + 2)       // 2176 float2 per data array (4352 floats)
#define TWN  (SKT(511) + 2)        // 576 float2 base twiddle table
#define TW16 256                   // 16x16 stage-1 twiddle table
#define STG_F2 264                 // 528-float output staging (4 planes x 132)
#define SMEM_F2 (2 * A2 + TWN + TW16 + STG_F2)
#define SMEM_BYTES (SMEM_F2 * 8)   // 43584

// ---------------- device statics ----------------
__device__ float2 g_bandT2[BW2 * N_MELS]; // [chunk][mel] = (tap 2c, tap 2c+1)
__device__ int    g_lo[N_MELS];           // align[m] (bank-permuted, may be <0)
__device__ int    g_nch[N_MELS];          // ceil(width'/8), 1..12
__device__ float  g_win[NFFT];
__device__ float2 g_tw2048[512];          // W_2048^k, k<512 (final-stage base)
__device__ float2 g_tw16[TW16];           // [k][p] = W_2048^{8pk}

// ---------------- single fused init: window/twiddles + scan + perm + band fill ----------------
__global__ __launch_bounds__(1024) void init_all(const float* __restrict__ fb) {
    __shared__ int slo[N_MELS], shi[N_MELS], salign[N_MELS], srlo[N_MELS], srhi[N_MELS];
    const int tid = threadIdx.x;

    // window + twiddle tables
    for (int i = tid; i < NFFT; i += 1024)
        g_win[i] = 0.5f - 0.5f * cospif((float)i / 1024.0f);
    if (tid < 512) {
        float s, c; sincospif(-(float)tid / 1024.0f, &s, &c);
        g_tw2048[tid] = make_float2(c, s);
    }
    if (tid < TW16) {                    // tw16[k*16+p] = W_2048^{8pk}
        int k = tid >> 4, p = tid & 15;
        float s, c; sincospif(-(float)(8 * p * k) / 1024.0f, &s, &c);
        g_tw16[tid] = make_float2(c, s);
    }

    // band extents scan
    if (tid < N_MELS) { slo[tid] = N_BINS; shi[tid] = -1; }
    __syncthreads();
    for (int idx = tid; idx < N_MELS * N_BINS; idx += 1024) {
        int m = idx / N_BINS;
        int k = idx - m * N_BINS;
        if (fb[idx] != 0.0f) { atomicMin(&slo[m], k); atomicMax(&shi[m], k); }
    }
    __syncthreads();

    // per-warp optimal bank permutation (threads 0..127 = 4 full warps)
    if (tid < N_MELS) {
        const int m = tid, lane = m & 31;
        const int lo = (shi[m] >= 0) ? slo[m] : 0;
        const int hi = (shi[m] >= 0) ? shi[m] : 0;
        const int width = hi - lo + 1;
        const int key = lo & 31;
        int rank = 0;
#pragma unroll
        for (int l = 0; l < 32; l++) {
            int ok = __shfl_sync(0xffffffffu, key, l);
            rank += (ok < key) || (ok == key && l < lane);
        }
        int best_s = 0, best_max = 1 << 30, best_sum = 1 << 30;
        for (int s = 0; s < 32; s++) {
            int tgt = (rank + s) & 31;
            int ext = (key - tgt) & 31;
            int val = width + ext;
            int vmax = __reduce_max_sync(0xffffffffu, val);
            int vsum = __reduce_add_sync(0xffffffffu, val);
            if (vmax < best_max || (vmax == best_max && vsum < best_sum)) {
                best_max = vmax; best_sum = vsum; best_s = s;
            }
        }
        const int tgt = (rank + best_s) & 31;
        const int align = lo - ((lo - tgt) & 31);   // ≡ tgt (mod 32), may be <0
        g_lo[m] = align;
        salign[m] = align; srlo[m] = lo; srhi[m] = hi;
        int wp = hi - align + 1;
        if (wp < 1) wp = 1;
        if (wp > BW) wp = BW;
        g_nch[m] = (wp + 7) >> 3;                   // 1..12
    }
    __syncthreads();

    // fill packed band table: g_bandT2[c*128+m] = (w[2c], w[2c+1]) rel. to align
    for (int idx = tid; idx < BW2 * N_MELS; idx += 1024) {
        int c = idx >> 7, m = idx & 127;
        int lo = srlo[m], hi = srhi[m], align = salign[m];
        int k0 = align + 2 * c, k1 = k0 + 1;
        float v0 = (k0 >= lo && k0 <= hi && k0 < N_BINS) ? fb[m * N_BINS + k0] : 0.0f;
        float v1 = (k1 >= lo && k1 <= hi && k1 < N_BINS) ? fb[m * N_BINS + k1] : 0.0f;
        g_bandT2[idx] = make_float2(v0, v1);
    }
}

// ---------------- complex helpers ----------------
__device__ __forceinline__ float2 cmul(float2 a, float2 b) {
    return make_float2(fmaf(a.x, b.x, -a.y * b.y), fmaf(a.x, b.y, a.y * b.x));
}
__device__ __forceinline__ float2 cadd(float2 a, float2 b) { return make_float2(a.x + b.x, a.y + b.y); }
__device__ __forceinline__ float2 csub(float2 a, float2 b) { return make_float2(a.x - b.x, a.y - b.y); }
__device__ __forceinline__ float2 cmulni(float2 a) { return make_float2(a.y, -a.x); }  // -i*a

// ---------------- radix-8 butterfly (DIT, natural order) ----------------
__device__ __forceinline__ void bfly8(float2* a) {
    const float C = 0.70710678118654752f;
    float2 s02 = cadd(a[0], a[4]), d02 = csub(a[0], a[4]);
    float2 s46 = cadd(a[2], a[6]), d46 = cmulni(csub(a[2], a[6]));
    float2 e0 = cadd(s02, s46), e2 = csub(s02, s46);
    float2 e1 = cadd(d02, d46), e3 = csub(d02, d46);
    float2 s13 = cadd(a[1], a[5]), d13 = csub(a[1], a[5]);
    float2 s57 = cadd(a[3], a[7]), d57 = cmulni(csub(a[3], a[7]));
    float2 o0 = cadd(s13, s57), o2 = csub(s13, s57);
    float2 o1 = cadd(d13, d57), o3 = csub(d13, d57);
    float2 t1 = make_float2(C * (o1.x + o1.y), C * (o1.y - o1.x));
    float2 t2 = cmulni(o2);
    float2 t3 = make_float2(C * (o3.y - o3.x), -C * (o3.x + o3.y));
    a[0] = cadd(e0, o0); a[4] = csub(e0, o0);
    a[1] = cadd(e1, t1); a[5] = csub(e1, t1);
    a[2] = cadd(e2, t2); a[6] = csub(e2, t2);
    a[3] = cadd(e3, t3); a[7] = csub(e3, t3);
}

// ---------------- radix-16 butterfly (4x4 Cooley-Tukey, natural order) ----------------
__device__ __forceinline__ void bfly16(float2* a) {
    const float C8 = 0.70710678118654752f;
    const float C1 = 0.92387953251128676f;   // cos(pi/8)
    const float S1 = 0.38268343236508977f;   // sin(pi/8)
    float2 B[4][4];
#pragma unroll
    for (int n2 = 0; n2 < 4; n2++) {
        float2 x0 = a[n2], x1 = a[n2 + 4], x2 = a[n2 + 8], x3 = a[n2 + 12];
        float2 t0 = cadd(x0, x2), t1 = csub(x0, x2);
        float2 t2 = cadd(x1, x3), t3 = cmulni(csub(x1, x3));
        B[n2][0] = cadd(t0, t2); B[n2][1] = cadd(t1, t3);
        B[n2][2] = csub(t0, t2); B[n2][3] = csub(t1, t3);
    }
    B[1][1] = cmul(B[1][1], make_float2(C1, -S1));
    B[1][2] = cmul(B[1][2], make_float2(C8, -C8));
    B[1][3] = cmul(B[1][3], make_float2(S1, -C1));
    B[2][1] = cmul(B[2][1], make_float2(C8, -C8));
    B[2][2] = cmulni(B[2][2]);
    B[2][3] = cmul(B[2][3], make_float2(-C8, -C8));
    B[3][1] = cmul(B[3][1], make_float2(S1, -C1));
    B[3][2] = cmul(B[3][2], make_float2(-C8, -C8));
    B[3][3] = cmul(B[3][3], make_float2(-C1, S1));
#pragma unroll
    for (int k1 = 0; k1 < 4; k1++) {
        float2 x0 = B[0][k1], x1 = B[1][k1], x2 = B[2][k1], x3 = B[3][k1];
        float2 t0 = cadd(x0, x2), t1 = csub(x0, x2);
        float2 t2 = cadd(x1, x3), t3 = cmulni(csub(x1, x3));
        a[k1]      = cadd(t0, t2);
        a[k1 + 4]  = cadd(t1, t3);
        a[k1 + 8]  = csub(t0, t2);
        a[k1 + 12] = csub(t1, t3);
    }
}

// ---------------- final radix-8 butterfly (L=256): Z[m] = Z[bf + 256m] ----------------
__device__ __forceinline__ void fft8_final(const float2* __restrict__ src,
                                           const float2* __restrict__ tws,
                                           int bf, float2* Z) {
#pragma unroll
    for (int k = 0; k < 8; k++) Z[k] = src[SKD(bf + 256 * k)];
    float2 w1 = tws[SKT(bf)];
    float2 w2 = cmul(w1, w1);
    float2 w3 = cmul(w2, w1);
    float2 w4 = cmul(w2, w2);       // depth-3 tree, not a serial chain
    float2 w5 = cmul(w2, w3);
    float2 w6 = cmul(w3, w3);
    float2 w7 = cmul(w3, w4);
    Z[1] = cmul(Z[1], w1);
    Z[2] = cmul(Z[2], w2);
    Z[3] = cmul(Z[3], w3);
    Z[4] = cmul(Z[4], w4);
    Z[5] = cmul(Z[5], w5);
    Z[6] = cmul(Z[6], w6);
    Z[7] = cmul(Z[7], w7);
    bfly8(Z);
}

// ---------------- fused: 2 frames/block, in-place radix-16/16/8 FFT + power + mel ----------------
__global__ __launch_bounds__(256, 4) void fft_mel_kernel(const float* __restrict__ x,
                                                         float* __restrict__ out) {
    extern __shared__ float2 smem[];
    float2* tws   = smem + 2 * A2;                 // 512-entry skewed (final stage)
    float2* tw16  = smem + 2 * A2 + TWN;           // 16x16 [k][p] (stage 1)
    float*  so    = (float*)(smem + 2 * A2 + TWN + TW16);  // output staging

    const int j  = threadIdx.x;
    const int f  = j >> 7;             // frame within block (0/1)
    const int jj = j & 127;
    const int t  = blockIdx.x * 2 + f;
    const int b  = blockIdx.y;
    const float2* xp = (const float2*)x + (size_t)b * S_LEN;  // (ch0, ch1)

    float2* za = smem + f * A2;        // single in-place array per frame

    for (int i = j; i < 512; i += 256) tws[SKT(i)] = g_tw2048[i];
    if (j < TW16) tw16[j] = g_tw16[j];

    // fused load + radix-16 stage 0 (L=1, unit twiddles): a_k = z[jj+128k] -> za[16jj+m]
    {
        const int base = t * HOP - 1024;
        float2 a[16];
        if (base >= 0 && base <= S_LEN - NFFT) {   // fast path: no reflection (1288/1292)
            const float2* xb = xp + base;
#pragma unroll
            for (int k = 0; k < 16; k++) {
                int n = jj + 128 * k;
                float2 v = __ldg(&xb[n]);
                float  w = g_win[n];
                a[k] = make_float2(w * v.x, w * v.y);
            }
        } else {
#pragma unroll
            for (int k = 0; k < 16; k++) {
                int n = jj + 128 * k;
                int p = base + n;
                p = (p < 0) ? -p : ((p >= S_LEN) ? 2 * S_LEN - 2 - p : p);
                float2 v = __ldg(&xp[p]);
                float  w = g_win[n];
                a[k] = make_float2(w * v.x, w * v.y);
            }
        }
        bfly16(a);
#pragma unroll
        for (int m = 0; m < 16; m++) za[SKD(16 * jj + m)] = a[m];
    }
    __syncthreads();

    // radix-16 stage 1 (L=16), IN-PLACE; twiddles via [k][p] table (conflict-free)
    {
        const int p = jj & 15;
        float2 a[16];
#pragma unroll
        for (int k = 0; k < 16; k++) a[k] = za[SKD(jj + 128 * k)];
#pragma unroll
        for (int k = 1; k < 16; k++) a[k] = cmul(a[k], tw16[k * 16 + p]);
        bfly16(a);
        __syncthreads();                // all reads complete before in-place writes
        const int o = ((jj >> 4) << 8) | p;
#pragma unroll
        for (int m = 0; m < 16; m++) za[SKD(o + 16 * m)] = a[m];
    }
    __syncthreads();

    // fused final radix-8 (L=256) + two-real unpack + power -> pw (aliases za)
    float* pw = (float*)za + PWBASE;    // 32-float negative-align guard precedes pw
    {
        const int bf0 = jj;
        const int bf1 = (jj == 0) ? 128 : 256 - jj;
        float2 ZA[8], ZB[8];
        fft8_final(za, tws, bf0, ZA);   // ZA[m] = Z[bf0 + 256m]
        fft8_final(za, tws, bf1, ZB);   // ZB[m] = Z[bf1 + 256m]
        __syncthreads();                // all reads complete before pw overwrites za

#define PWR(K, ZK, ZN)                                                  \
        {                                                               \
            float sr = (ZK).x + (ZN).x, si = (ZK).y - (ZN).y;           \
            float dr = (ZK).x - (ZN).x, di = (ZK).y + (ZN).y;           \
            pw[(K)]       = 0.25f * (sr * sr + si * si);                \
            pw[PWS + (K)] = 0.25f * (di * di + dr * dr);                \
        }
        if (jj == 0) {
            PWR(0,    ZA[0], ZA[0]);
            PWR(256,  ZA[1], ZA[7]);
            PWR(512,  ZA[2], ZA[6]);
            PWR(768,  ZA[3], ZA[5]);
            PWR(1024, ZA[4], ZA[4]);
#pragma unroll
            for (int m = 0; m < 4; m++) PWR(128 + 256 * m, ZB[m], ZB[7 - m]);
        } else {
#pragma unroll
            for (int m = 0; m < 4; m++) {
                PWR(jj + 256 * m,         ZA[m], ZB[7 - m]);   // Z[k], Z[2048-k]
                PWR((256 - jj) + 256 * m, ZB[m], ZA[7 - m]);
            }
        }
#undef PWR
    }
    // zero guards: leading 32 floats (negative aligns) + tails of both channels
    if (jj < PWBASE) ((float*)za)[jj] = 0.0f;
#pragma unroll
    for (int i = jj; i < (PWS - N_BINS); i += 128) {
        pw[N_BINS + i]       = 0.0f;
        pw[PWS + N_BINS + i] = 0.0f;
    }
    __syncthreads();

    // banded mel: thread j -> mel m = j&127, channel ch = j>>7, BOTH frames
    const int ch = j >> 7;
    const int m  = j & 127;
    const int lo = g_lo[m];             // permuted-aligned window start (may be <0)
    const float* p0 = (const float*)(smem)      + PWBASE + ch * PWS + lo;   // frame 0
    const float* p1 = (const float*)(smem + A2) + PWBASE + ch * PWS + lo;   // frame 1
    const float2* bt2 = g_bandT2 + m;   // column m, row stride 128 float2 (coalesced)
    const int umax = __reduce_max_sync(0xffffffffu, g_nch[m]);
    float q0 = 0.0f, q1 = 0.0f, q2 = 0.0f, q3 = 0.0f;   // frame 0
    float r0 = 0.0f, r1 = 0.0f, r2 = 0.0f, r3 = 0.0f;   // frame 1

#define MEL_DOT(TAPS)                                                   \
    _Pragma("unroll")                                                   \
    for (int c = 0; c < (TAPS) / 2; c += 2) {                           \
        float2 BA = bt2[c * N_MELS];                                    \
        float2 BB = bt2[(c + 1) * N_MELS];                              \
        int i = 2 * c;                                                  \
        q0 = fmaf(BA.x, p0[i],     q0);  r0 = fmaf(BA.x, p1[i],     r0); \
        q1 = fmaf(BA.y, p0[i + 1], q1);  r1 = fmaf(BA.y, p1[i + 1], r1); \
        q2 = fmaf(BB.x, p0[i + 2], q2);  r2 = fmaf(BB.x, p1[i + 2], r2); \
        q3 = fmaf(BB.y, p0[i + 3], q3);  r3 = fmaf(BB.y, p1[i + 3], r3); \
    }

    switch (umax) {
        case 1:  MEL_DOT(8);  break;
        case 2:  MEL_DOT(16); break;
        case 3:  MEL_DOT(24); break;
        case 4:  MEL_DOT(32); break;
        case 5:  MEL_DOT(40); break;
        case 6:  MEL_DOT(48); break;
        case 7:  MEL_DOT(56); break;
        case 8:  MEL_DOT(64); break;
        case 9:  MEL_DOT(72); break;
        case 10: MEL_DOT(80); break;
        case 11: MEL_DOT(88); break;
        default: MEL_DOT(96); break;
    }
#undef MEL_DOT

    // stage results, then coalesced float4 stores: out float4 = (f0c0,f0c1,f1c0,f1c1)
    so[(0 * 2 + ch) * 132 + m] = (q0 + q1) + (q2 + q3);   // frame 0
    so[(1 * 2 + ch) * 132 + m] = (r0 + r1) + (r2 + r3);   // frame 1
    __syncthreads();
    if (j < 128) {
        float4 v = make_float4(so[j], so[132 + j], so[264 + j], so[396 + j]);
        *(float4*)(out + (((size_t)b * N_MELS + j) * T_FRAMES + blockIdx.x * 2) * 2) = v;
    }
}

// ---------------- entry point ----------------
extern "C" void kernel_launch(void* const* d_in, const int* in_sizes, int n_in,
                              void* d_out, int out_size) {
    const float* x  = (const float*)d_in[0];   // (8, 661500, 2) f32
    const float* fb = (const float*)d_in[1];   // (128, 1025)   f32
    float* out = (float*)d_out;                // (8, 128, 1292, 2) f32

    cudaFuncSetAttribute(fft_mel_kernel,
                         cudaFuncAttributeMaxDynamicSharedMemorySize, SMEM_BYTES);
    init_all<<<1, 1024>>>(fb);
    fft_mel_kernel<<<dim3(T_FRAMES / 2, 8), 256, SMEM_BYTES>>>(x, out);
}

// round 15
// speedup vs baseline: 1.0556x; 1.0556x over previous
#include <cuda_runtime.h>
#include <cuda_bf16.h>

// ---------------- problem constants ----------------
#define S_LEN    661500
#define HOP      512
#define NFFT     2048
#define T_FRAMES 1292
#define N_BINS   1025
#define N_MELS   128
#define BW       96                // mel band window cap
#define BW2      (BW / 2)          // float2 chunks
#define PWS      1088              // power row stride (34*32)
#define PWBASE   32                // pw starts 32 floats in (neg-align guard)

// smem skews (index units: float2)
#define SKD(i) ((i) + ((i) >> 4))  // data arrays
#define SKT(i) ((i) + ((i) >> 3))  // twiddle table

#define A2   (SKD(2047) + 2)       // 2176 float2 per data array (4352 floats)
#define TWN  (SKT(511) + 2)        // 576 float2 base twiddle table
#define TW16 256                   // 16x16 stage-1 twiddle table
#define STG_F2 264                 // 528-float output staging (4 planes x 132)
#define SMEM_F2 (2 * A2 + TWN + TW16 + STG_F2)
#define SMEM_BYTES (SMEM_F2 * 8)   // 43584

// half-scoped named barrier: frame-half f uses barrier id f+1, 128 threads
#define BAR_HALF(f) asm volatile("bar.sync %0, 128;" :: "r"((f) + 1) : "memory")

// ---------------- device statics ----------------
__device__ float2 g_bandT2[BW2 * N_MELS]; // [chunk][mel] = (tap 2c, tap 2c+1)
__device__ int    g_lo[N_MELS];           // align[m] (bank-permuted, may be <0)
__device__ int    g_nch[N_MELS];          // ceil(width'/8), 1..12
__device__ int    g_rawlo[N_MELS], g_rawhi[N_MELS];
__device__ float  g_win[NFFT];
__device__ float2 g_tw2048[512];          // W_2048^k, k<512 (final-stage base)
__device__ float2 g_tw16[TW16];           // [k][p] = W_2048^{8pk}

// ---------------- init pass 1 (parallel): extents scan + window + twiddles ----------------
__global__ void init_scan(const float* __restrict__ fb) {
    const int tid = threadIdx.x;
    if (blockIdx.x == 128) {
        for (int i = tid; i < NFFT; i += 256)
            g_win[i] = 0.5f - 0.5f * cospif((float)i / 1024.0f);
        for (int i = tid; i < 512; i += 256) {
            float s, c; sincospif(-(float)i / 1024.0f, &s, &c);
            g_tw2048[i] = make_float2(c, s);
        }
        if (tid < TW16) {                    // tw16[k*16+p] = W_2048^{8pk}
            int k = tid >> 4, p = tid & 15;
            float s, c; sincospif(-(float)(8 * p * k) / 1024.0f, &s, &c);
            g_tw16[tid] = make_float2(c, s);
        }
        return;
    }
    __shared__ int slo, shi;
    const int m = blockIdx.x;
    if (tid == 0) { slo = N_BINS; shi = -1; }
    __syncthreads();
    int l = N_BINS, h = -1;
    for (int k = tid; k < N_BINS; k += blockDim.x) {
        if (fb[m * N_BINS + k] != 0.0f) { l = min(l, k); h = max(h, k); }
    }
    atomicMin(&slo, l);
    atomicMax(&shi, h);
    __syncthreads();
    if (tid == 0) {
        g_rawlo[m] = (shi >= 0) ? slo : 0;
        g_rawhi[m] = (shi >= 0) ? shi : 0;
    }
}

// ---------------- init pass 2: per-warp bank permutation + packed band fill ----------------
__global__ __launch_bounds__(1024) void init_perm(const float* __restrict__ fb) {
    __shared__ int salign[N_MELS], srlo[N_MELS], srhi[N_MELS];
    const int tid = threadIdx.x;

    if (tid < N_MELS) {                  // warps 0-3, all lanes active
        const int m = tid, lane = m & 31;
        const int lo = g_rawlo[m];
        const int hi = g_rawhi[m];
        const int width = hi - lo + 1;
        const int key = lo & 31;
        int rank = 0;
#pragma unroll
        for (int l = 0; l < 32; l++) {
            int ok = __shfl_sync(0xffffffffu, key, l);
            rank += (ok < key) || (ok == key && l < lane);
        }
        int best_s = 0, best_max = 1 << 30, best_sum = 1 << 30;
        for (int s = 0; s < 32; s++) {
            int tgt = (rank + s) & 31;
            int ext = (key - tgt) & 31;
            int val = width + ext;
            int vmax = __reduce_max_sync(0xffffffffu, val);
            int vsum = __reduce_add_sync(0xffffffffu, val);
            if (vmax < best_max || (vmax == best_max && vsum < best_sum)) {
                best_max = vmax; best_sum = vsum; best_s = s;
            }
        }
        const int tgt = (rank + best_s) & 31;
        const int align = lo - ((lo - tgt) & 31);   // ≡ tgt (mod 32), may be <0
        g_lo[m] = align;
        salign[m] = align; srlo[m] = lo; srhi[m] = hi;
        int wp = hi - align + 1;
        if (wp < 1) wp = 1;
        if (wp > BW) wp = BW;
        g_nch[m] = (wp + 7) >> 3;                   // 1..12
    }
    __syncthreads();

    // fill packed band table: g_bandT2[c*128+m] = (w[2c], w[2c+1]) rel. to align
    for (int idx = tid; idx < BW2 * N_MELS; idx += 1024) {
        int c = idx >> 7, m = idx & 127;
        int lo = srlo[m], hi = srhi[m], align = salign[m];
        int k0 = align + 2 * c, k1 = k0 + 1;
        float v0 = (k0 >= lo && k0 <= hi && k0 < N_BINS) ? fb[m * N_BINS + k0] : 0.0f;
        float v1 = (k1 >= lo && k1 <= hi && k1 < N_BINS) ? fb[m * N_BINS + k1] : 0.0f;
        g_bandT2[idx] = make_float2(v0, v1);
    }
}

// ---------------- complex helpers ----------------
__device__ __forceinline__ float2 cmul(float2 a, float2 b) {
    return make_float2(fmaf(a.x, b.x, -a.y * b.y), fmaf(a.x, b.y, a.y * b.x));
}
__device__ __forceinline__ float2 cadd(float2 a, float2 b) { return make_float2(a.x + b.x, a.y + b.y); }
__device__ __forceinline__ float2 csub(float2 a, float2 b) { return make_float2(a.x - b.x, a.y - b.y); }
__device__ __forceinline__ float2 cmulni(float2 a) { return make_float2(a.y, -a.x); }  // -i*a

// ---------------- radix-8 butterfly (DIT, natural order) ----------------
__device__ __forceinline__ void bfly8(float2* a) {
    const float C = 0.70710678118654752f;
    float2 s02 = cadd(a[0], a[4]), d02 = csub(a[0], a[4]);
    float2 s46 = cadd(a[2], a[6]), d46 = cmulni(csub(a[2], a[6]));
    float2 e0 = cadd(s02, s46), e2 = csub(s02, s46);
    float2 e1 = cadd(d02, d46), e3 = csub(d02, d46);
    float2 s13 = cadd(a[1], a[5]), d13 = csub(a[1], a[5]);
    float2 s57 = cadd(a[3], a[7]), d57 = cmulni(csub(a[3], a[7]));
    float2 o0 = cadd(s13, s57), o2 = csub(s13, s57);
    float2 o1 = cadd(d13, d57), o3 = csub(d13, d57);
    float2 t1 = make_float2(C * (o1.x + o1.y), C * (o1.y - o1.x));
    float2 t2 = cmulni(o2);
    float2 t3 = make_float2(C * (o3.y - o3.x), -C * (o3.x + o3.y));
    a[0] = cadd(e0, o0); a[4] = csub(e0, o0);
    a[1] = cadd(e1, t1); a[5] = csub(e1, t1);
    a[2] = cadd(e2, t2); a[6] = csub(e2, t2);
    a[3] = cadd(e3, t3); a[7] = csub(e3, t3);
}

// ---------------- radix-16 butterfly (4x4 Cooley-Tukey, natural order) ----------------
__device__ __forceinline__ void bfly16(float2* a) {
    const float C8 = 0.70710678118654752f;
    const float C1 = 0.92387953251128676f;   // cos(pi/8)
    const float S1 = 0.38268343236508977f;   // sin(pi/8)
    float2 B[4][4];
#pragma unroll
    for (int n2 = 0; n2 < 4; n2++) {
        float2 x0 = a[n2], x1 = a[n2 + 4], x2 = a[n2 + 8], x3 = a[n2 + 12];
        float2 t0 = cadd(x0, x2), t1 = csub(x0, x2);
        float2 t2 = cadd(x1, x3), t3 = cmulni(csub(x1, x3));
        B[n2][0] = cadd(t0, t2); B[n2][1] = cadd(t1, t3);
        B[n2][2] = csub(t0, t2); B[n2][3] = csub(t1, t3);
    }
    B[1][1] = cmul(B[1][1], make_float2(C1, -S1));
    B[1][2] = cmul(B[1][2], make_float2(C8, -C8));
    B[1][3] = cmul(B[1][3], make_float2(S1, -C1));
    B[2][1] = cmul(B[2][1], make_float2(C8, -C8));
    B[2][2] = cmulni(B[2][2]);
    B[2][3] = cmul(B[2][3], make_float2(-C8, -C8));
    B[3][1] = cmul(B[3][1], make_float2(S1, -C1));
    B[3][2] = cmul(B[3][2], make_float2(-C8, -C8));
    B[3][3] = cmul(B[3][3], make_float2(-C1, S1));
#pragma unroll
    for (int k1 = 0; k1 < 4; k1++) {
        float2 x0 = B[0][k1], x1 = B[1][k1], x2 = B[2][k1], x3 = B[3][k1];
        float2 t0 = cadd(x0, x2), t1 = csub(x0, x2);
        float2 t2 = cadd(x1, x3), t3 = cmulni(csub(x1, x3));
        a[k1]      = cadd(t0, t2);
        a[k1 + 4]  = cadd(t1, t3);
        a[k1 + 8]  = csub(t0, t2);
        a[k1 + 12] = csub(t1, t3);
    }
}

// ---------------- final radix-8 butterfly (L=256): Z[m] = Z[bf + 256m] ----------------
__device__ __forceinline__ void fft8_final(const float2* __restrict__ src,
                                           const float2* __restrict__ tws,
                                           int bf, float2* Z) {
#pragma unroll
    for (int k = 0; k < 8; k++) Z[k] = src[SKD(bf + 256 * k)];
    float2 w1 = tws[SKT(bf)];
    float2 w2 = cmul(w1, w1);
    float2 w3 = cmul(w2, w1);
    float2 w4 = cmul(w2, w2);       // depth-3 tree
    float2 w5 = cmul(w2, w3);
    float2 w6 = cmul(w3, w3);
    float2 w7 = cmul(w3, w4);
    Z[1] = cmul(Z[1], w1);
    Z[2] = cmul(Z[2], w2);
    Z[3] = cmul(Z[3], w3);
    Z[4] = cmul(Z[4], w4);
    Z[5] = cmul(Z[5], w5);
    Z[6] = cmul(Z[6], w6);
    Z[7] = cmul(Z[7], w7);
    bfly8(Z);
}

// ---------------- fused: 2 frames/block (half-decoupled), FFT + power + mel ----------------
__global__ __launch_bounds__(256, 4) void fft_mel_kernel(const float* __restrict__ x,
                                                         float* __restrict__ out) {
    extern __shared__ float2 smem[];
    float2* tws   = smem + 2 * A2;                 // 512-entry skewed (final stage)
    float2* tw16  = smem + 2 * A2 + TWN;           // 16x16 [k][p] (stage 1)
    float*  so    = (float*)(smem + 2 * A2 + TWN + TW16);  // output staging

    const int j  = threadIdx.x;
    const int f  = j >> 7;             // frame within block (0/1); warps 0-3 / 4-7
    const int jj = j & 127;
    const int t  = blockIdx.x * 2 + f;
    const int b  = blockIdx.y;
    const float2* xp = (const float2*)x + (size_t)b * S_LEN;  // (ch0, ch1)

    float2* za = smem + f * A2;        // this half's in-place array

    for (int i = j; i < 512; i += 256) tws[SKT(i)] = g_tw2048[i];
    if (j < TW16) tw16[j] = g_tw16[j];

    // fused load + radix-16 stage 0 (L=1, unit twiddles): a_k = z[jj+128k] -> za[16jj+m]
    {
        const int base = t * HOP - 1024;
        float2 a[16];
        if (base >= 0 && base <= S_LEN - NFFT) {   // fast path (1288/1292 frames)
            const float2* xb = xp + base;
#pragma unroll
            for (int k = 0; k < 16; k++) {
                int n = jj + 128 * k;
                float2 v = __ldg(&xb[n]);
                float  w = g_win[n];
                a[k] = make_float2(w * v.x, w * v.y);
            }
        } else {
#pragma unroll
            for (int k = 0; k < 16; k++) {
                int n = jj + 128 * k;
                int p = base + n;
                p = (p < 0) ? -p : ((p >= S_LEN) ? 2 * S_LEN - 2 - p : p);
                float2 v = __ldg(&xp[p]);
                float  w = g_win[n];
                a[k] = make_float2(w * v.x, w * v.y);
            }
        }
        bfly16(a);
#pragma unroll
        for (int m = 0; m < 16; m++) za[SKD(16 * jj + m)] = a[m];
    }
    __syncthreads();   // FULL: publishes twiddle tables (staged by both halves) + za

    // radix-16 stage 1 (L=16), IN-PLACE, half-scoped sync
    {
        const int p = jj & 15;
        float2 a[16];
#pragma unroll
        for (int k = 0; k < 16; k++) a[k] = za[SKD(jj + 128 * k)];
#pragma unroll
        for (int k = 1; k < 16; k++) a[k] = cmul(a[k], tw16[k * 16 + p]);
        bfly16(a);
        BAR_HALF(f);                    // own half's reads complete
        const int o = ((jj >> 4) << 8) | p;
#pragma unroll
        for (int m = 0; m < 16; m++) za[SKD(o + 16 * m)] = a[m];
    }
    BAR_HALF(f);

    // fused final radix-8 (L=256) + two-real unpack + power -> pw (aliases za)
    float* pw = (float*)za + PWBASE;    // 32-float negative-align guard precedes pw
    {
        const int bf0 = jj;
        const int bf1 = (jj == 0) ? 128 : 256 - jj;
        float2 ZA[8], ZB[8];
        fft8_final(za, tws, bf0, ZA);   // ZA[m] = Z[bf0 + 256m]
        fft8_final(za, tws, bf1, ZB);   // ZB[m] = Z[bf1 + 256m]
        BAR_HALF(f);                    // own half's reads complete before overwrite

#define PWR(K, ZK, ZN)                                                  \
        {                                                               \
            float sr = (ZK).x + (ZN).x, si = (ZK).y - (ZN).y;           \
            float dr = (ZK).x - (ZN).x, di = (ZK).y + (ZN).y;           \
            pw[(K)]       = 0.25f * (sr * sr + si * si);                \
            pw[PWS + (K)] = 0.25f * (di * di + dr * dr);                \
        }
        if (jj == 0) {
            PWR(0,    ZA[0], ZA[0]);
            PWR(256,  ZA[1], ZA[7]);
            PWR(512,  ZA[2], ZA[6]);
            PWR(768,  ZA[3], ZA[5]);
            PWR(1024, ZA[4], ZA[4]);
#pragma unroll
            for (int m = 0; m < 4; m++) PWR(128 + 256 * m, ZB[m], ZB[7 - m]);
        } else {
#pragma unroll
            for (int m = 0; m < 4; m++) {
                PWR(jj + 256 * m,         ZA[m], ZB[7 - m]);   // Z[k], Z[2048-k]
                PWR((256 - jj) + 256 * m, ZB[m], ZA[7 - m]);
            }
        }
#undef PWR
    }
    // zero guards: leading 32 floats (negative aligns) + tails of both channels
    if (jj < PWBASE) ((float*)za)[jj] = 0.0f;
#pragma unroll
    for (int i = jj; i < (PWS - N_BINS); i += 128) {
        pw[N_BINS + i]       = 0.0f;
        pw[PWS + N_BINS + i] = 0.0f;
    }
    BAR_HALF(f);

    // banded mel, half-local: thread (f, jj) -> mel m = jj, BOTH channels of frame f
    const int m  = jj;
    const int lo = g_lo[m];             // permuted-aligned window start (may be <0)
    const float* p0 = (const float*)za + PWBASE + lo;         // ch0, own frame
    const float* p1 = (const float*)za + PWBASE + PWS + lo;   // ch1, own frame
    const float2* bt2 = g_bandT2 + m;   // column m, row stride 128 float2 (coalesced)
    const int umax = __reduce_max_sync(0xffffffffu, g_nch[m]);
    float q0 = 0.0f, q1 = 0.0f, q2 = 0.0f, q3 = 0.0f;   // ch0
    float r0 = 0.0f, r1 = 0.0f, r2 = 0.0f, r3 = 0.0f;   // ch1

#define MEL_DOT(TAPS)                                                   \
    _Pragma("unroll")                                                   \
    for (int c = 0; c < (TAPS) / 2; c += 2) {                           \
        float2 BA = bt2[c * N_MELS];                                    \
        float2 BB = bt2[(c + 1) * N_MELS];                              \
        int i = 2 * c;                                                  \
        q0 = fmaf(BA.x, p0[i],     q0);  r0 = fmaf(BA.x, p1[i],     r0); \
        q1 = fmaf(BA.y, p0[i + 1], q1);  r1 = fmaf(BA.y, p1[i + 1], r1); \
        q2 = fmaf(BB.x, p0[i + 2], q2);  r2 = fmaf(BB.x, p1[i + 2], r2); \
        q3 = fmaf(BB.y, p0[i + 3], q3);  r3 = fmaf(BB.y, p1[i + 3], r3); \
    }

    switch (umax) {
        case 1:  MEL_DOT(8);  break;
        case 2:  MEL_DOT(16); break;
        case 3:  MEL_DOT(24); break;
        case 4:  MEL_DOT(32); break;
        case 5:  MEL_DOT(40); break;
        case 6:  MEL_DOT(48); break;
        case 7:  MEL_DOT(56); break;
        case 8:  MEL_DOT(64); break;
        case 9:  MEL_DOT(72); break;
        case 10: MEL_DOT(80); break;
        case 11: MEL_DOT(88); break;
        default: MEL_DOT(96); break;
    }
#undef MEL_DOT

    // stage results, then coalesced float4 stores: out float4 = (f0c0,f0c1,f1c0,f1c1)
    so[(f * 2 + 0) * 132 + m] = (q0 + q1) + (q2 + q3);   // ch0
    so[(f * 2 + 1) * 132 + m] = (r0 + r1) + (r2 + r3);   // ch1
    __syncthreads();   // FULL: both halves' results needed for packed store
    if (j < 128) {
        float4 v = make_float4(so[j], so[132 + j], so[264 + j], so[396 + j]);
        *(float4*)(out + (((size_t)b * N_MELS + j) * T_FRAMES + blockIdx.x * 2) * 2) = v;
    }
}

// ---------------- entry point ----------------
extern "C" void kernel_launch(void* const* d_in, const int* in_sizes, int n_in,
                              void* d_out, int out_size) {
    const float* x  = (const float*)d_in[0];   // (8, 661500, 2) f32
    const float* fb = (const float*)d_in[1];   // (128, 1025)   f32
    float* out = (float*)d_out;                // (8, 128, 1292, 2) f32

    cudaFuncSetAttribute(fft_mel_kernel,
                         cudaFuncAttributeMaxDynamicSharedMemorySize, SMEM_BYTES);
    init_scan<<<129, 256>>>(fb);
    init_perm<<<1, 1024>>>(fb);
    fft_mel_kernel<<<dim3(T_FRAMES / 2, 8), 256, SMEM_BYTES>>>(x, out);
}

// round 16
// speedup vs baseline: 1.0888x; 1.0315x over previous
#include <cuda_runtime.h>
#include <cuda_bf16.h>

// ---------------- problem constants ----------------
#define S_LEN    661500
#define HOP      512
#define NFFT     2048
#define T_FRAMES 1292
#define N_BINS   1025
#define N_MELS   128
#define BW       96                // mel band window cap (width<=54 + even-ext<=31)
#define BW2      (BW / 2)          // float2 chunks
#define PWS      1088              // power row stride (34*32)
#define PWBASE   32                // pw starts 32 floats in (neg-align guard)

// smem skews (index units: float2)
#define SKD(i) ((i) + ((i) >> 4))  // data arrays
#define SKT(i) ((i) + ((i) >> 3))  // twiddle table

#define A2   (SKD(2047) + 2)       // 2176 float2 per data array (4352 floats)
#define TWN  (SKT(511) + 2)        // 576 float2 base twiddle table
#define TW16 256                   // 16x16 stage-1 twiddle table
#define STG_F2 264                 // 528-float output staging (4 planes x 132)
#define SMEM_F2 (2 * A2 + TWN + TW16 + STG_F2)
#define SMEM_BYTES (SMEM_F2 * 8)   // 43584

// half-scoped named barrier: frame-half f uses barrier id f+1, 128 threads
#define BAR_HALF(f) asm volatile("bar.sync %0, 128;" :: "r"((f) + 1) : "memory")

// packed f32x2 fma: acc = a*b + acc (componentwise)
#define FMA2(acc, a, b) \
    asm("fma.rn.f32x2 %0, %1, %2, %0;" : "+l"(acc) : "l"(a), "l"(b))

// ---------------- device statics ----------------
__device__ float2 g_bandT2[BW2 * N_MELS]; // [chunk][mel] = (tap 2c, tap 2c+1)
__device__ int    g_lo[N_MELS];           // align[m] (even, half-warp-permuted, may be <0)
__device__ int    g_nch[N_MELS];          // ceil(width'/8), 1..12
__device__ int    g_rawlo[N_MELS], g_rawhi[N_MELS];
__device__ float  g_win[NFFT];
__device__ float2 g_tw2048[512];          // W_2048^k, k<512 (final-stage base)
__device__ float2 g_tw16[TW16];           // [k][p] = W_2048^{8pk}

// ---------------- init pass 1 (parallel): extents scan + window + twiddles ----------------
__global__ void init_scan(const float* __restrict__ fb) {
    const int tid = threadIdx.x;
    if (blockIdx.x == 128) {
        for (int i = tid; i < NFFT; i += 256)
            g_win[i] = 0.5f - 0.5f * cospif((float)i / 1024.0f);
        for (int i = tid; i < 512; i += 256) {
            float s, c; sincospif(-(float)i / 1024.0f, &s, &c);
            g_tw2048[i] = make_float2(c, s);
        }
        if (tid < TW16) {                    // tw16[k*16+p] = W_2048^{8pk}
            int k = tid >> 4, p = tid & 15;
            float s, c; sincospif(-(float)(8 * p * k) / 1024.0f, &s, &c);
            g_tw16[tid] = make_float2(c, s);
        }
        return;
    }
    __shared__ int slo, shi;
    const int m = blockIdx.x;
    if (tid == 0) { slo = N_BINS; shi = -1; }
    __syncthreads();
    int l = N_BINS, h = -1;
    for (int k = tid; k < N_BINS; k += blockDim.x) {
        if (fb[m * N_BINS + k] != 0.0f) { l = min(l, k); h = max(h, k); }
    }
    atomicMin(&slo, l);
    atomicMax(&shi, h);
    __syncthreads();
    if (tid == 0) {
        g_rawlo[m] = (shi >= 0) ? slo : 0;
        g_rawhi[m] = (shi >= 0) ? shi : 0;
    }
}

// ---------------- init pass 2: per-HALF-WARP even-bank permutation + packed band fill ----------------
__global__ __launch_bounds__(1024) void init_perm(const float* __restrict__ fb) {
    __shared__ int salign[N_MELS], srlo[N_MELS], srhi[N_MELS];
    const int tid = threadIdx.x;

    if (tid < N_MELS) {                  // warps 0-3, all lanes active
        const int m = tid;
        const int hl = m & 15;           // lane within 16-lane half-warp segment
        const int lo = g_rawlo[m];
        const int hi = g_rawhi[m];
        const int width = hi - lo + 1;
        const int key = lo & 31;

        // rank within the 16-lane segment (stable, tie-break by lane)
        int rank = 0;
#pragma unroll
        for (int l = 0; l < 16; l++) {
            int ok = __shfl_sync(0xffffffffu, key, l, 16);
            rank += (ok < key) || (ok == key && l < hl);
        }
        // choose cyclic shift s: tgt = 2*((rank+s)&15) (even banks, bijective per
        // segment); minimize segment-max(width + ext), tie: min segment-sum
        int best_s = 0, best_max = 1 << 30, best_sum = 1 << 30;
        for (int s = 0; s < 16; s++) {
            int tgt = 2 * ((rank + s) & 15);
            int ext = (key - tgt) & 31;
            int val = width + ext;
            int vmax = val, vsum = val;
#pragma unroll
            for (int d = 8; d; d >>= 1) {
                vmax = max(vmax, __shfl_xor_sync(0xffffffffu, vmax, d, 16));
                vsum += __shfl_xor_sync(0xffffffffu, vsum, d, 16);
            }
            if (vmax < best_max || (vmax == best_max && vsum < best_sum)) {
                best_max = vmax; best_sum = vsum; best_s = s;
            }
        }
        const int tgt = 2 * ((rank + best_s) & 15);
        const int align = lo - ((lo - tgt) & 31);   // ≡ tgt (mod 32), EVEN, may be <0
        g_lo[m] = align;
        salign[m] = align; srlo[m] = lo; srhi[m] = hi;
        int wp = hi - align + 1;
        if (wp < 1) wp = 1;
        if (wp > BW) wp = BW;
        g_nch[m] = (wp + 7) >> 3;                   // 1..12
    }
    __syncthreads();

    // fill packed band table: g_bandT2[c*128+m] = (w[2c], w[2c+1]) rel. to align
    for (int idx = tid; idx < BW2 * N_MELS; idx += 1024) {
        int c = idx >> 7, m = idx & 127;
        int lo = srlo[m], hi = srhi[m], align = salign[m];
        int k0 = align + 2 * c, k1 = k0 + 1;
        float v0 = (k0 >= lo && k0 <= hi && k0 < N_BINS) ? fb[m * N_BINS + k0] : 0.0f;
        float v1 = (k1 >= lo && k1 <= hi && k1 < N_BINS) ? fb[m * N_BINS + k1] : 0.0f;
        g_bandT2[idx] = make_float2(v0, v1);
    }
}

// ---------------- complex helpers ----------------
__device__ __forceinline__ float2 cmul(float2 a, float2 b) {
    return make_float2(fmaf(a.x, b.x, -a.y * b.y), fmaf(a.x, b.y, a.y * b.x));
}
__device__ __forceinline__ float2 cadd(float2 a, float2 b) { return make_float2(a.x + b.x, a.y + b.y); }
__device__ __forceinline__ float2 csub(float2 a, float2 b) { return make_float2(a.x - b.x, a.y - b.y); }
__device__ __forceinline__ float2 cmulni(float2 a) { return make_float2(a.y, -a.x); }  // -i*a

// ---------------- radix-8 butterfly (DIT, natural order) ----------------
__device__ __forceinline__ void bfly8(float2* a) {
    const float C = 0.70710678118654752f;
    float2 s02 = cadd(a[0], a[4]), d02 = csub(a[0], a[4]);
    float2 s46 = cadd(a[2], a[6]), d46 = cmulni(csub(a[2], a[6]));
    float2 e0 = cadd(s02, s46), e2 = csub(s02, s46);
    float2 e1 = cadd(d02, d46), e3 = csub(d02, d46);
    float2 s13 = cadd(a[1], a[5]), d13 = csub(a[1], a[5]);
    float2 s57 = cadd(a[3], a[7]), d57 = cmulni(csub(a[3], a[7]));
    float2 o0 = cadd(s13, s57), o2 = csub(s13, s57);
    float2 o1 = cadd(d13, d57), o3 = csub(d13, d57);
    float2 t1 = make_float2(C * (o1.x + o1.y), C * (o1.y - o1.x));
    float2 t2 = cmulni(o2);
    float2 t3 = make_float2(C * (o3.y - o3.x), -C * (o3.x + o3.y));
    a[0] = cadd(e0, o0); a[4] = csub(e0, o0);
    a[1] = cadd(e1, t1); a[5] = csub(e1, t1);
    a[2] = cadd(e2, t2); a[6] = csub(e2, t2);
    a[3] = cadd(e3, t3); a[7] = csub(e3, t3);
}

// ---------------- radix-16 butterfly (4x4 Cooley-Tukey, natural order) ----------------
__device__ __forceinline__ void bfly16(float2* a) {
    const float C8 = 0.70710678118654752f;
    const float C1 = 0.92387953251128676f;   // cos(pi/8)
    const float S1 = 0.38268343236508977f;   // sin(pi/8)
    float2 B[4][4];
#pragma unroll
    for (int n2 = 0; n2 < 4; n2++) {
        float2 x0 = a[n2], x1 = a[n2 + 4], x2 = a[n2 + 8], x3 = a[n2 + 12];
        float2 t0 = cadd(x0, x2), t1 = csub(x0, x2);
        float2 t2 = cadd(x1, x3), t3 = cmulni(csub(x1, x3));
        B[n2][0] = cadd(t0, t2); B[n2][1] = cadd(t1, t3);
        B[n2][2] = csub(t0, t2); B[n2][3] = csub(t1, t3);
    }
    B[1][1] = cmul(B[1][1], make_float2(C1, -S1));
    B[1][2] = cmul(B[1][2], make_float2(C8, -C8));
    B[1][3] = cmul(B[1][3], make_float2(S1, -C1));
    B[2][1] = cmul(B[2][1], make_float2(C8, -C8));
    B[2][2] = cmulni(B[2][2]);
    B[2][3] = cmul(B[2][3], make_float2(-C8, -C8));
    B[3][1] = cmul(B[3][1], make_float2(S1, -C1));
    B[3][2] = cmul(B[3][2], make_float2(-C8, -C8));
    B[3][3] = cmul(B[3][3], make_float2(-C1, S1));
#pragma unroll
    for (int k1 = 0; k1 < 4; k1++) {
        float2 x0 = B[0][k1], x1 = B[1][k1], x2 = B[2][k1], x3 = B[3][k1];
        float2 t0 = cadd(x0, x2), t1 = csub(x0, x2);
        float2 t2 = cadd(x1, x3), t3 = cmulni(csub(x1, x3));
        a[k1]      = cadd(t0, t2);
        a[k1 + 4]  = cadd(t1, t3);
        a[k1 + 8]  = csub(t0, t2);
        a[k1 + 12] = csub(t1, t3);
    }
}

// ---------------- final radix-8 butterfly (L=256): Z[m] = Z[bf + 256m] ----------------
__device__ __forceinline__ void fft8_final(const float2* __restrict__ src,
                                           const float2* __restrict__ tws,
                                           int bf, float2* Z) {
#pragma unroll
    for (int k = 0; k < 8; k++) Z[k] = src[SKD(bf + 256 * k)];
    float2 w1 = tws[SKT(bf)];
    float2 w2 = cmul(w1, w1);
    float2 w3 = cmul(w2, w1);
    float2 w4 = cmul(w2, w2);       // depth-3 tree
    float2 w5 = cmul(w2, w3);
    float2 w6 = cmul(w3, w3);
    float2 w7 = cmul(w3, w4);
    Z[1] = cmul(Z[1], w1);
    Z[2] = cmul(Z[2], w2);
    Z[3] = cmul(Z[3], w3);
    Z[4] = cmul(Z[4], w4);
    Z[5] = cmul(Z[5], w5);
    Z[6] = cmul(Z[6], w6);
    Z[7] = cmul(Z[7], w7);
    bfly8(Z);
}

// ---------------- fused: 2 frames/block (half-decoupled), FFT + power + mel ----------------
__global__ __launch_bounds__(256, 4) void fft_mel_kernel(const float* __restrict__ x,
                                                         float* __restrict__ out) {
    extern __shared__ float2 smem[];
    float2* tws   = smem + 2 * A2;                 // 512-entry skewed (final stage)
    float2* tw16  = smem + 2 * A2 + TWN;           // 16x16 [k][p] (stage 1)
    float*  so    = (float*)(smem + 2 * A2 + TWN + TW16);  // output staging

    const int j  = threadIdx.x;
    const int f  = j >> 7;             // frame within block (0/1); warps 0-3 / 4-7
    const int jj = j & 127;
    const int t  = blockIdx.x * 2 + f;
    const int b  = blockIdx.y;
    const float2* xp = (const float2*)x + (size_t)b * S_LEN;  // (ch0, ch1)

    float2* za = smem + f * A2;        // this half's in-place array

    for (int i = j; i < 512; i += 256) tws[SKT(i)] = g_tw2048[i];
    if (j < TW16) tw16[j] = g_tw16[j];

    // fused load + radix-16 stage 0 (L=1, unit twiddles): a_k = z[jj+128k] -> za[16jj+m]
    {
        const int base = t * HOP - 1024;
        float2 a[16];
        if (base >= 0 && base <= S_LEN - NFFT) {   // fast path (1288/1292 frames)
            const float2* xb = xp + base;
#pragma unroll
            for (int k = 0; k < 16; k++) {
                int n = jj + 128 * k;
                float2 v = __ldg(&xb[n]);
                float  w = g_win[n];
                a[k] = make_float2(w * v.x, w * v.y);
            }
        } else {
#pragma unroll
            for (int k = 0; k < 16; k++) {
                int n = jj + 128 * k;
                int p = base + n;
                p = (p < 0) ? -p : ((p >= S_LEN) ? 2 * S_LEN - 2 - p : p);
                float2 v = __ldg(&xp[p]);
                float  w = g_win[n];
                a[k] = make_float2(w * v.x, w * v.y);
            }
        }
        bfly16(a);
#pragma unroll
        for (int m = 0; m < 16; m++) za[SKD(16 * jj + m)] = a[m];
    }
    __syncthreads();   // FULL: publishes twiddle tables (staged by both halves) + za

    // radix-16 stage 1 (L=16), IN-PLACE, half-scoped sync
    {
        const int p = jj & 15;
        float2 a[16];
#pragma unroll
        for (int k = 0; k < 16; k++) a[k] = za[SKD(jj + 128 * k)];
#pragma unroll
        for (int k = 1; k < 16; k++) a[k] = cmul(a[k], tw16[k * 16 + p]);
        bfly16(a);
        BAR_HALF(f);                    // own half's reads complete
        const int o = ((jj >> 4) << 8) | p;
#pragma unroll
        for (int m = 0; m < 16; m++) za[SKD(o + 16 * m)] = a[m];
    }
    BAR_HALF(f);

    // fused final radix-8 (L=256) + two-real unpack + power -> pw (aliases za)
    float* pw = (float*)za + PWBASE;    // 32-float negative-align guard precedes pw
    {
        const int bf0 = jj;
        const int bf1 = (jj == 0) ? 128 : 256 - jj;
        float2 ZA[8], ZB[8];
        fft8_final(za, tws, bf0, ZA);   // ZA[m] = Z[bf0 + 256m]
        fft8_final(za, tws, bf1, ZB);   // ZB[m] = Z[bf1 + 256m]
        BAR_HALF(f);                    // own half's reads complete before overwrite

#define PWR(K, ZK, ZN)                                                  \
        {                                                               \
            float sr = (ZK).x + (ZN).x, si = (ZK).y - (ZN).y;           \
            float dr = (ZK).x - (ZN).x, di = (ZK).y + (ZN).y;           \
            pw[(K)]       = 0.25f * (sr * sr + si * si);                \
            pw[PWS + (K)] = 0.25f * (di * di + dr * dr);                \
        }
        if (jj == 0) {
            PWR(0,    ZA[0], ZA[0]);
            PWR(256,  ZA[1], ZA[7]);
            PWR(512,  ZA[2], ZA[6]);
            PWR(768,  ZA[3], ZA[5]);
            PWR(1024, ZA[4], ZA[4]);
#pragma unroll
            for (int m = 0; m < 4; m++) PWR(128 + 256 * m, ZB[m], ZB[7 - m]);
        } else {
#pragma unroll
            for (int m = 0; m < 4; m++) {
                PWR(jj + 256 * m,         ZA[m], ZB[7 - m]);   // Z[k], Z[2048-k]
                PWR((256 - jj) + 256 * m, ZB[m], ZA[7 - m]);
            }
        }
#undef PWR
    }
    // zero guards: leading 32 floats (negative aligns) + tails of both channels
    if (jj < PWBASE) ((float*)za)[jj] = 0.0f;
#pragma unroll
    for (int i = jj; i < (PWS - N_BINS); i += 128) {
        pw[N_BINS + i]       = 0.0f;
        pw[PWS + N_BINS + i] = 0.0f;
    }
    BAR_HALF(f);

    // banded mel, half-local: thread (f, jj) -> mel m = jj, BOTH channels of frame f.
    // align is EVEN and a bijection onto even banks per 16-lane half-warp
    // ⇒ LDS.64 is conflict-free; packed fma.rn.f32x2 does 2 taps/instr.
    const int m  = jj;
    const int lo = g_lo[m];             // even aligned window start (may be <0)
    const float2* p0v = (const float2*)((const float*)za + PWBASE + lo);        // ch0
    const float2* p1v = (const float2*)((const float*)za + PWBASE + PWS + lo);  // ch1
    const float2* bt2 = g_bandT2 + m;   // column m, row stride 128 float2 (coalesced)
    const int umax = __reduce_max_sync(0xffffffffu, g_nch[m]);
    unsigned long long aq0 = 0ull, aq1 = 0ull;   // packed ch0 accumulators
    unsigned long long ar0 = 0ull, ar1 = 0ull;   // packed ch1 accumulators

#define MEL_DOT(TAPS)                                                       \
    _Pragma("unroll")                                                       \
    for (int c = 0; c < (TAPS) / 2; c += 2) {                               \
        unsigned long long BA  = *(const unsigned long long*)&bt2[c * N_MELS];       \
        unsigned long long BB  = *(const unsigned long long*)&bt2[(c + 1) * N_MELS]; \
        unsigned long long P0A = *(const unsigned long long*)&p0v[c];       \
        unsigned long long P0B = *(const unsigned long long*)&p0v[c + 1];   \
        unsigned long long P1A = *(const unsigned long long*)&p1v[c];       \
        unsigned long long P1B = *(const unsigned long long*)&p1v[c + 1];   \
        FMA2(aq0, BA, P0A);  FMA2(aq1, BB, P0B);                            \
        FMA2(ar0, BA, P1A);  FMA2(ar1, BB, P1B);                            \
    }

    switch (umax) {
        case 1:  MEL_DOT(8);  break;
        case 2:  MEL_DOT(16); break;
        case 3:  MEL_DOT(24); break;
        case 4:  MEL_DOT(32); break;
        case 5:  MEL_DOT(40); break;
        case 6:  MEL_DOT(48); break;
        case 7:  MEL_DOT(56); break;
        case 8:  MEL_DOT(64); break;
        case 9:  MEL_DOT(72); break;
        case 10: MEL_DOT(80); break;
        case 11: MEL_DOT(88); break;
        default: MEL_DOT(96); break;
    }
#undef MEL_DOT

    float q0x, q0y, q1x, q1y, r0x, r0y, r1x, r1y;
    asm("mov.b64 {%0, %1}, %2;" : "=f"(q0x), "=f"(q0y) : "l"(aq0));
    asm("mov.b64 {%0, %1}, %2;" : "=f"(q1x), "=f"(q1y) : "l"(aq1));
    asm("mov.b64 {%0, %1}, %2;" : "=f"(r0x), "=f"(r0y) : "l"(ar0));
    asm("mov.b64 {%0, %1}, %2;" : "=f"(r1x), "=f"(r1y) : "l"(ar1));

    // stage results, then coalesced float4 stores: out float4 = (f0c0,f0c1,f1c0,f1c1)
    so[(f * 2 + 0) * 132 + m] = (q0x + q0y) + (q1x + q1y);   // ch0
    so[(f * 2 + 1) * 132 + m] = (r0x + r0y) + (r1x + r1y);   // ch1
    __syncthreads();   // FULL: both halves' results needed for packed store
    if (j < 128) {
        float4 v = make_float4(so[j], so[132 + j], so[264 + j], so[396 + j]);
        *(float4*)(out + (((size_t)b * N_MELS + j) * T_FRAMES + blockIdx.x * 2) * 2) = v;
    }
}

// ---------------- entry point ----------------
extern "C" void kernel_launch(void* const* d_in, const int* in_sizes, int n_in,
                              void* d_out, int out_size) {
    const float* x  = (const float*)d_in[0];   // (8, 661500, 2) f32
    const float* fb = (const float*)d_in[1];   // (128, 1025)   f32
    float* out = (float*)d_out;                // (8, 128, 1292, 2) f32

    cudaFuncSetAttribute(fft_mel_kernel,
                         cudaFuncAttributeMaxDynamicSharedMemorySize, SMEM_BYTES);
    init_scan<<<129, 256>>>(fb);
    init_perm<<<1, 1024>>>(fb);
    fft_mel_kernel<<<dim3(T_FRAMES / 2, 8), 256, SMEM_BYTES>>>(x, out);
}

// round 17
// speedup vs baseline: 1.1503x; 1.0565x over previous
#include <cuda_runtime.h>
#include <cuda_bf16.h>

// ---------------- problem constants ----------------
#define S_LEN    661500
#define HOP      512
#define NFFT     2048
#define T_FRAMES 1292
#define N_BINS   1025
#define N_MELS   128
#define BW       96                // mel band window cap (width<=54 + even-ext<=31)
#define BW2      (BW / 2)          // float2 chunks
#define PWS      1088              // power row stride (34*32)
#define PWBASE   32                // pw starts 32 floats in (neg-align guard)

// smem skews (index units: float2)
#define SKD(i) ((i) + ((i) >> 4))  // data arrays
#define SKT(i) ((i) + ((i) >> 3))  // twiddle table

#define A2   (SKD(2047) + 2)       // 2176 float2 per data array (4352 floats)
#define TWN  (SKT(511) + 2)        // 576 float2 base twiddle table
#define TW16 256                   // 16x16 stage-1 twiddle table
#define STG_F2 264                 // 528-float output staging (4 planes x 132)
#define SMEM_F2 (2 * A2 + TWN + TW16 + STG_F2)
#define SMEM_BYTES (SMEM_F2 * 8)   // 43584

// half-scoped named barrier: frame-half f uses barrier id f+1, 128 threads
#define BAR_HALF(f) asm volatile("bar.sync %0, 128;" :: "r"((f) + 1) : "memory")

typedef unsigned long long u64;

// packed f32x2 constants (lo = .x, hi = .y)
#define K_NEG1 0xBF800000BF800000ULL   // (-1, -1)
#define K_PMI  0xBF8000003F800000ULL   // (+1, -1)
#define K_MIP  0x3F800000BF800000ULL   // (-1, +1)

// ---------------- packed f32x2 helpers ----------------
__device__ __forceinline__ u64 pk2(float x, float y) {
    u64 r; asm("mov.b64 %0, {%1, %2};" : "=l"(r) : "f"(x), "f"(y)); return r;
}
__device__ __forceinline__ float2 upk(u64 a) {
    float2 r; asm("mov.b64 {%0, %1}, %2;" : "=f"(r.x), "=f"(r.y) : "l"(a)); return r;
}
__device__ __forceinline__ u64 padd(u64 a, u64 b) {
    u64 r; asm("add.rn.f32x2 %0, %1, %2;" : "=l"(r) : "l"(a), "l"(b)); return r;
}
__device__ __forceinline__ u64 pmul(u64 a, u64 b) {
    u64 r; asm("mul.rn.f32x2 %0, %1, %2;" : "=l"(r) : "l"(a), "l"(b)); return r;
}
__device__ __forceinline__ u64 pfma(u64 a, u64 b, u64 c) {   // a*b + c
    u64 r; asm("fma.rn.f32x2 %0, %1, %2, %3;" : "=l"(r) : "l"(a), "l"(b), "l"(c)); return r;
}
__device__ __forceinline__ u64 psub(u64 a, u64 b) { return pfma(b, K_NEG1, a); }  // a - b
__device__ __forceinline__ u64 pswap(u64 a) { float2 t = upk(a); return pk2(t.y, t.x); }
// packed fma accumulate (mel loop)
#define FMA2(acc, a, b) \
    asm("fma.rn.f32x2 %0, %1, %2, %0;" : "+l"(acc) : "l"(a), "l"(b))

// complex multiply: packed value * float2 twiddle (scalar core, packed I/O)
__device__ __forceinline__ float2 cmul(float2 a, float2 b) {
    return make_float2(fmaf(a.x, b.x, -a.y * b.y), fmaf(a.x, b.y, a.y * b.x));
}
__device__ __forceinline__ u64 pcmul(u64 a, float2 w) {
    float2 f = upk(a);
    return pk2(fmaf(f.x, w.x, -f.y * w.y), fmaf(f.x, w.y, f.y * w.x));
}
__device__ __forceinline__ u64 pcmulc(u64 a, float cr, float ci) {
    float2 f = upk(a);
    return pk2(fmaf(f.x, cr, -f.y * ci), fmaf(f.x, ci, f.y * cr));
}

// ---------------- device statics ----------------
__device__ float2 g_bandT2[BW2 * N_MELS]; // [chunk][mel] = (tap 2c, tap 2c+1)
__device__ int    g_lo[N_MELS];           // align[m] (even, half-warp-permuted, may be <0)
__device__ int    g_nch[N_MELS];          // ceil(width'/8), 1..12
__device__ int    g_rawlo[N_MELS], g_rawhi[N_MELS];
__device__ float  g_win[NFFT];
__device__ float2 g_tw2048[512];          // W_2048^k, k<512 (final-stage base)
__device__ float2 g_tw16[TW16];           // [k][p] = W_2048^{8pk}
__device__ int    g_cnt;                  // scan-completion ticket (reset each call)

// ---------------- single init kernel: scan blocks + tables block; last block perms ----------------
__global__ __launch_bounds__(256) void init_all(const float* __restrict__ fb) {
    const int tid = threadIdx.x;
    if (blockIdx.x == 128) {               // window + twiddle tables (independent)
        for (int i = tid; i < NFFT; i += 256)
            g_win[i] = 0.5f - 0.5f * cospif((float)i / 1024.0f);
        for (int i = tid; i < 512; i += 256) {
            float s, c; sincospif(-(float)i / 1024.0f, &s, &c);
            g_tw2048[i] = make_float2(c, s);
        }
        if (tid < TW16) {
            int k = tid >> 4, p = tid & 15;
            float s, c; sincospif(-(float)(8 * p * k) / 1024.0f, &s, &c);
            g_tw16[tid] = make_float2(c, s);
        }
        return;
    }
    // --- scan extents for mel m = blockIdx.x ---
    __shared__ int slo, shi;
    __shared__ int is_last;
    const int mb = blockIdx.x;
    if (tid == 0) { slo = N_BINS; shi = -1; }
    __syncthreads();
    int l = N_BINS, h = -1;
    for (int k = tid; k < N_BINS; k += 256) {
        if (fb[mb * N_BINS + k] != 0.0f) { l = min(l, k); h = max(h, k); }
    }
    atomicMin(&slo, l);
    atomicMax(&shi, h);
    __syncthreads();
    if (tid == 0) {
        g_rawlo[mb] = (shi >= 0) ? slo : 0;
        g_rawhi[mb] = (shi >= 0) ? shi : 0;
        __threadfence();
        is_last = (atomicAdd(&g_cnt, 1) == 127);
    }
    __syncthreads();
    if (!is_last) return;
    __threadfence();   // acquire all scan blocks' writes

    // --- last scan block: per-half-warp even-bank permutation + packed band fill ---
    __shared__ int salign[N_MELS], srlo[N_MELS], srhi[N_MELS];
    if (tid < N_MELS) {                  // warps 0-3, all lanes active
        const int m = tid;
        const int hl = m & 15;
        const int lo = g_rawlo[m];
        const int hi = g_rawhi[m];
        const int width = hi - lo + 1;
        const int key = lo & 31;
        int rank = 0;
#pragma unroll
        for (int q = 0; q < 16; q++) {
            int ok = __shfl_sync(0xffffffffu, key, q, 16);
            rank += (ok < key) || (ok == key && q < hl);
        }
        int best_s = 0, best_max = 1 << 30, best_sum = 1 << 30;
        for (int s = 0; s < 16; s++) {
            int tgt = 2 * ((rank + s) & 15);
            int ext = (key - tgt) & 31;
            int val = width + ext;
            int vmax = val, vsum = val;
#pragma unroll
            for (int d = 8; d; d >>= 1) {
                vmax = max(vmax, __shfl_xor_sync(0xffffffffu, vmax, d, 16));
                vsum += __shfl_xor_sync(0xffffffffu, vsum, d, 16);
            }
            if (vmax < best_max || (vmax == best_max && vsum < best_sum)) {
                best_max = vmax; best_sum = vsum; best_s = s;
            }
        }
        const int tgt = 2 * ((rank + best_s) & 15);
        const int align = lo - ((lo - tgt) & 31);   // ≡ tgt (mod 32), EVEN, may be <0
        g_lo[m] = align;
        salign[m] = align; srlo[m] = lo; srhi[m] = hi;
        int wp = hi - align + 1;
        if (wp < 1) wp = 1;
        if (wp > BW) wp = BW;
        g_nch[m] = (wp + 7) >> 3;                   // 1..12
    }
    __syncthreads();
    for (int idx = tid; idx < BW2 * N_MELS; idx += 256) {
        int c = idx >> 7, m = idx & 127;
        int lo = srlo[m], hi = srhi[m], align = salign[m];
        int k0 = align + 2 * c, k1 = k0 + 1;
        float v0 = (k0 >= lo && k0 <= hi && k0 < N_BINS) ? fb[m * N_BINS + k0] : 0.0f;
        float v1 = (k1 >= lo && k1 <= hi && k1 < N_BINS) ? fb[m * N_BINS + k1] : 0.0f;
        g_bandT2[idx] = make_float2(v0, v1);
    }
    if (tid == 0) { __threadfence(); g_cnt = 0; }   // reset ticket for graph replay
}

// ---------------- packed radix-8 butterfly (DIT, natural order) ----------------
__device__ __forceinline__ void pbfly8(u64* a) {
    const float C = 0.70710678118654752f;
    u64 s02 = padd(a[0], a[4]), d02 = psub(a[0], a[4]);
    u64 s46 = padd(a[2], a[6]);
    u64 sd46 = pswap(psub(a[2], a[6]));
    u64 e0 = padd(s02, s46), e2 = psub(s02, s46);
    u64 e1 = pfma(sd46, K_PMI, d02);            // d02 + ni(d46)
    u64 e3 = pfma(sd46, K_MIP, d02);            // d02 - ni(d46)
    u64 s13 = padd(a[1], a[5]), d13 = psub(a[1], a[5]);
    u64 s57 = padd(a[3], a[7]);
    u64 sd57 = pswap(psub(a[3], a[7]));
    u64 o0 = padd(s13, s57), o2 = psub(s13, s57);
    u64 o1 = pfma(sd57, K_PMI, d13);
    u64 o3 = pfma(sd57, K_MIP, d13);
    float2 o1f = upk(o1);
    u64 t1 = pk2(C * (o1f.x + o1f.y), C * (o1f.y - o1f.x));
    u64 t2 = pmul(pswap(o2), K_PMI);            // -i*o2
    float2 o3f = upk(o3);
    u64 t3 = pk2(C * (o3f.y - o3f.x), -C * (o3f.x + o3f.y));
    a[0] = padd(e0, o0); a[4] = psub(e0, o0);
    a[1] = padd(e1, t1); a[5] = psub(e1, t1);
    a[2] = padd(e2, t2); a[6] = psub(e2, t2);
    a[3] = padd(e3, t3); a[7] = psub(e3, t3);
}

// ---------------- packed radix-16 butterfly (4x4 Cooley-Tukey, natural order) ----------------
__device__ __forceinline__ void pbfly16(u64* a) {
    const float C8 = 0.70710678118654752f;
    const float C1 = 0.92387953251128676f;   // cos(pi/8)
    const float S1 = 0.38268343236508977f;   // sin(pi/8)
    u64 B[4][4];
#pragma unroll
    for (int n2 = 0; n2 < 4; n2++) {
        u64 x0 = a[n2], x1 = a[n2 + 4], x2 = a[n2 + 8], x3 = a[n2 + 12];
        u64 t0 = padd(x0, x2), t1 = psub(x0, x2);
        u64 t2 = padd(x1, x3);
        u64 sd = pswap(psub(x1, x3));
        B[n2][0] = padd(t0, t2);
        B[n2][2] = psub(t0, t2);
        B[n2][1] = pfma(sd, K_PMI, t1);         // t1 + ni(d)
        B[n2][3] = pfma(sd, K_MIP, t1);         // t1 - ni(d)
    }
    B[1][1] = pcmulc(B[1][1], C1, -S1);
    B[1][2] = pcmulc(B[1][2], C8, -C8);
    B[1][3] = pcmulc(B[1][3], S1, -C1);
    B[2][1] = pcmulc(B[2][1], C8, -C8);
    B[2][2] = pmul(pswap(B[2][2]), K_PMI);      // -i
    B[2][3] = pcmulc(B[2][3], -C8, -C8);
    B[3][1] = pcmulc(B[3][1], S1, -C1);
    B[3][2] = pcmulc(B[3][2], -C8, -C8);
    B[3][3] = pcmulc(B[3][3], -C1, S1);
#pragma unroll
    for (int k1 = 0; k1 < 4; k1++) {
        u64 x0 = B[0][k1], x1 = B[1][k1], x2 = B[2][k1], x3 = B[3][k1];
        u64 t0 = padd(x0, x2), t1 = psub(x0, x2);
        u64 t2 = padd(x1, x3);
        u64 sd = pswap(psub(x1, x3));
        a[k1]      = padd(t0, t2);
        a[k1 + 8]  = psub(t0, t2);
        a[k1 + 4]  = pfma(sd, K_PMI, t1);
        a[k1 + 12] = pfma(sd, K_MIP, t1);
    }
}

// ---------------- final radix-8 butterfly (L=256): Z[m] = Z[bf + 256m] ----------------
__device__ __forceinline__ void pfft8_final(const u64* __restrict__ src,
                                            const float2* __restrict__ tws,
                                            int bf, u64* Z) {
#pragma unroll
    for (int k = 0; k < 8; k++) Z[k] = src[SKD(bf + 256 * k)];
    float2 w1 = tws[SKT(bf)];
    float2 w2 = cmul(w1, w1);
    float2 w3 = cmul(w2, w1);
    float2 w4 = cmul(w2, w2);       // depth-3 tree
    float2 w5 = cmul(w2, w3);
    float2 w6 = cmul(w3, w3);
    float2 w7 = cmul(w3, w4);
    Z[1] = pcmul(Z[1], w1);
    Z[2] = pcmul(Z[2], w2);
    Z[3] = pcmul(Z[3], w3);
    Z[4] = pcmul(Z[4], w4);
    Z[5] = pcmul(Z[5], w5);
    Z[6] = pcmul(Z[6], w6);
    Z[7] = pcmul(Z[7], w7);
    pbfly8(Z);
}

// ---------------- fused: 2 frames/block (half-decoupled), FFT + power + mel ----------------
__global__ __launch_bounds__(256, 4) void fft_mel_kernel(const float* __restrict__ x,
                                                         float* __restrict__ out) {
    extern __shared__ float2 smem[];
    float2* tws   = smem + 2 * A2;                 // 512-entry skewed (final stage)
    float2* tw16  = smem + 2 * A2 + TWN;           // 16x16 [k][p] (stage 1)
    float*  so    = (float*)(smem + 2 * A2 + TWN + TW16);  // output staging

    const int j  = threadIdx.x;
    const int f  = j >> 7;             // frame within block (0/1); warps 0-3 / 4-7
    const int jj = j & 127;
    const int t  = blockIdx.x * 2 + f;
    const int b  = blockIdx.y;
    const float2* xp = (const float2*)x + (size_t)b * S_LEN;  // (ch0, ch1)

    u64* za = (u64*)(smem + f * A2);   // this half's in-place array (packed complex)

    for (int i = j; i < 512; i += 256) tws[SKT(i)] = g_tw2048[i];
    if (j < TW16) tw16[j] = g_tw16[j];

    // fused load + radix-16 stage 0 (L=1, unit twiddles): a_k = z[jj+128k] -> za[16jj+m]
    {
        const int base = t * HOP - 1024;
        u64 a[16];
        if (base >= 0 && base <= S_LEN - NFFT) {   // fast path (1288/1292 frames)
            const float2* xb = xp + base;
#pragma unroll
            for (int k = 0; k < 16; k++) {
                int n = jj + 128 * k;
                float2 v = __ldg(&xb[n]);
                float  w = g_win[n];
                a[k] = pk2(w * v.x, w * v.y);
            }
        } else {
#pragma unroll
            for (int k = 0; k < 16; k++) {
                int n = jj + 128 * k;
                int p = base + n;
                p = (p < 0) ? -p : ((p >= S_LEN) ? 2 * S_LEN - 2 - p : p);
                float2 v = __ldg(&xp[p]);
                float  w = g_win[n];
                a[k] = pk2(w * v.x, w * v.y);
            }
        }
        pbfly16(a);
#pragma unroll
        for (int m = 0; m < 16; m++) za[SKD(16 * jj + m)] = a[m];
    }
    __syncthreads();   // FULL: publishes twiddle tables (staged by both halves) + za

    // radix-16 stage 1 (L=16), IN-PLACE, half-scoped sync
    {
        const int p = jj & 15;
        u64 a[16];
#pragma unroll
        for (int k = 0; k < 16; k++) a[k] = za[SKD(jj + 128 * k)];
#pragma unroll
        for (int k = 1; k < 16; k++) a[k] = pcmul(a[k], tw16[k * 16 + p]);
        pbfly16(a);
        BAR_HALF(f);                    // own half's reads complete
        const int o = ((jj >> 4) << 8) | p;
#pragma unroll
        for (int m = 0; m < 16; m++) za[SKD(o + 16 * m)] = a[m];
    }
    BAR_HALF(f);

    // fused final radix-8 (L=256) + two-real unpack + power -> pw (aliases za)
    float* pw = (float*)za + PWBASE;    // 32-float negative-align guard precedes pw
    {
        const int bf0 = jj;
        const int bf1 = (jj == 0) ? 128 : 256 - jj;
        u64 ZA[8], ZB[8];
        pfft8_final(za, tws, bf0, ZA);  // ZA[m] = Z[bf0 + 256m]
        pfft8_final(za, tws, bf1, ZB);  // ZB[m] = Z[bf1 + 256m]
        BAR_HALF(f);                    // own half's reads complete before overwrite

#define PWR(K, ZK, ZN)                                                  \
        {                                                               \
            float2 s = upk(pfma((ZN), K_PMI, (ZK)));  /* (sr, si) */    \
            float2 d = upk(pfma((ZN), K_MIP, (ZK)));  /* (dr, di) */    \
            pw[(K)]       = 0.25f * fmaf(s.x, s.x, s.y * s.y);          \
            pw[PWS + (K)] = 0.25f * fmaf(d.x, d.x, d.y * d.y);          \
        }
        if (jj == 0) {
            PWR(0,    ZA[0], ZA[0]);
            PWR(256,  ZA[1], ZA[7]);
            PWR(512,  ZA[2], ZA[6]);
            PWR(768,  ZA[3], ZA[5]);
            PWR(1024, ZA[4], ZA[4]);
#pragma unroll
            for (int m = 0; m < 4; m++) PWR(128 + 256 * m, ZB[m], ZB[7 - m]);
        } else {
#pragma unroll
            for (int m = 0; m < 4; m++) {
                PWR(jj + 256 * m,         ZA[m], ZB[7 - m]);   // Z[k], Z[2048-k]
                PWR((256 - jj) + 256 * m, ZB[m], ZA[7 - m]);
            }
        }
#undef PWR
    }
    // zero guards: leading 32 floats (negative aligns) + tails of both channels
    if (jj < PWBASE) ((float*)za)[jj] = 0.0f;
#pragma unroll
    for (int i = jj; i < (PWS - N_BINS); i += 128) {
        pw[N_BINS + i]       = 0.0f;
        pw[PWS + N_BINS + i] = 0.0f;
    }
    BAR_HALF(f);

    // banded mel, half-local: thread (f, jj) -> mel m = jj, BOTH channels of frame f.
    // even-bank bijective alignment per 16-lane half-warp ⇒ conflict-free LDS.64.
    const int m  = jj;
    const int lo = g_lo[m];             // even aligned window start (may be <0)
    const float2* p0v = (const float2*)((const float*)za + PWBASE + lo);        // ch0
    const float2* p1v = (const float2*)((const float*)za + PWBASE + PWS + lo);  // ch1
    const float2* bt2 = g_bandT2 + m;   // column m, row stride 128 float2 (coalesced)
    const int umax = __reduce_max_sync(0xffffffffu, g_nch[m]);
    u64 aq0 = 0ull, aq1 = 0ull;   // packed ch0 accumulators
    u64 ar0 = 0ull, ar1 = 0ull;   // packed ch1 accumulators

#define MEL_DOT(TAPS)                                                       \
    _Pragma("unroll")                                                       \
    for (int c = 0; c < (TAPS) / 2; c += 2) {                               \
        u64 BA  = *(const u64*)&bt2[c * N_MELS];                            \
        u64 BB  = *(const u64*)&bt2[(c + 1) * N_MELS];                      \
        u64 P0A = *(const u64*)&p0v[c];                                     \
        u64 P0B = *(const u64*)&p0v[c + 1];                                 \
        u64 P1A = *(const u64*)&p1v[c];                                     \
        u64 P1B = *(const u64*)&p1v[c + 1];                                 \
        FMA2(aq0, BA, P0A);  FMA2(aq1, BB, P0B);                            \
        FMA2(ar0, BA, P1A);  FMA2(ar1, BB, P1B);                            \
    }

    switch (umax) {
        case 1:  MEL_DOT(8);  break;
        case 2:  MEL_DOT(16); break;
        case 3:  MEL_DOT(24); break;
        case 4:  MEL_DOT(32); break;
        case 5:  MEL_DOT(40); break;
        case 6:  MEL_DOT(48); break;
        case 7:  MEL_DOT(56); break;
        case 8:  MEL_DOT(64); break;
        case 9:  MEL_DOT(72); break;
        case 10: MEL_DOT(80); break;
        case 11: MEL_DOT(88); break;
        default: MEL_DOT(96); break;
    }
#undef MEL_DOT

    float2 q0 = upk(aq0), q1 = upk(aq1), r0 = upk(ar0), r1 = upk(ar1);

    // stage results, then coalesced float4 stores: out float4 = (f0c0,f0c1,f1c0,f1c1)
    so[(f * 2 + 0) * 132 + m] = (q0.x + q0.y) + (q1.x + q1.y);   // ch0
    so[(f * 2 + 1) * 132 + m] = (r0.x + r0.y) + (r1.x + r1.y);   // ch1
    __syncthreads();   // FULL: both halves' results needed for packed store
    if (j < 128) {
        float4 v = make_float4(so[j], so[132 + j], so[264 + j], so[396 + j]);
        *(float4*)(out + (((size_t)b * N_MELS + j) * T_FRAMES + blockIdx.x * 2) * 2) = v;
    }
}

// ---------------- entry point ----------------
extern "C" void kernel_launch(void* const* d_in, const int* in_sizes, int n_in,
                              void* d_out, int out_size) {
    const float* x  = (const float*)d_in[0];   // (8, 661500, 2) f32
    const float* fb = (const float*)d_in[1];   // (128, 1025)   f32
    float* out = (float*)d_out;                // (8, 128, 1292, 2) f32

    cudaFuncSetAttribute(fft_mel_kernel,
                         cudaFuncAttributeMaxDynamicSharedMemorySize, SMEM_BYTES);
    init_all<<<129, 256>>>(fb);
    fft_mel_kernel<<<dim3(T_FRAMES / 2, 8), 256, SMEM_BYTES>>>(x, out);
}